// round 16
// baseline (speedup 1.0000x reference)
#include <cuda_runtime.h>
#include <stdint.h>

// SRP map on GB300 — round 12.
//
// maps[f,g] = sum_{k!=l} x[f, k*12+l, tau0[k,l,g]], then per-frame
// zero-mean + /max. Wrapped lags in {0..7} U {504..511} -> 16 slots.
//
// R12 vs R15 (18.9us, 4-frame attempt poisoned by mov.b64 repacking,
// regs 64) and R13-best (17.2us total, 2-frame):
//  * 4 frames/CTA KEPT, movs DELETED: LDS.128 loads land directly as
//    ulonglong2 — .x = packed f32x2 of frames(0,1), .y = frames(2,3).
//    Chunk body: LDS.32 tau + 4x(PRMT+IADD+LDS.128) + 8xFADD2 = 21 inst
//    per 16 frame-values, no repacking, ~40 regs.
//  * 4 llu accumulators (2 per frame-half, ping-pong): 8-cyc chain per
//    chunk << 21-cyc issue.
//  * grid 1024 CTAs fully resident (no wave transition); smem 26KB.
//  * Kept (verified): pair folding, diagonal drop, hoisted fold table,
//    cp.async staging, coalesced tau, fused last-CTA normalization.

#define KLEN    512
#define GPTS    2048
#define THREADS 128
#define NFOLD   66
#define NROWS   68
#define NENT    (NROWS * 16)        // 1088 entries
#define NCHUNK  17
#define NSPLIT  16
#define NF4     64                  // frame quads
#define PACK_BLOCKS (NCHUNK * 32)   // 544
#define FOLD_SPLIT 4

__constant__ uint8_t c_pairA[NFOLD] = {
  1,2,3,4,5,6,7,8,9,10,11,
  14,15,16,17,18,19,20,21,22,23,
  27,28,29,30,31,32,33,34,35,
  40,41,42,43,44,45,46,47,
  53,54,55,56,57,58,59,
  66,67,68,69,70,71,
  79,80,81,82,83,
  92,93,94,95,
  105,106,107,
  118,119,
  131};
__constant__ uint8_t c_pairB[NFOLD] = {
  12,24,36,48,60,72,84,96,108,120,132,
  25,37,49,61,73,85,97,109,121,133,
  38,50,62,74,86,98,110,122,134,
  51,63,75,87,99,111,123,135,
  64,76,88,100,112,124,136,
  77,89,101,113,125,137,
  90,102,114,126,138,
  103,115,127,139,
  116,128,140,
  129,141,
  142};

// g_tauB[c*2048+g]: 4 bytes = slot*16 (LDS.128 offset) for pairs 4c..4c+3.
__device__ __align__(16) uint32_t g_tauB[NCHUNK * GPTS];
// folded x table: y4[f4][entry] = (y_f0, y_f1, y_f2, y_f3)
__device__ __align__(16) float4 g_y4[NF4 * NENT];          // 4.5 MB
// last-arrival workspace
__device__ float ws_s[256 * NSPLIT];
__device__ float ws_m[256 * NSPLIT];
__device__ int   ws_c[NF4];              // zero-init; self-resetting

__device__ __forceinline__ int lag_of(int s) { return (s < 8) ? s : (s + 496); }

__device__ __forceinline__ uint32_t smem_u32(const void* p) {
    return (uint32_t)__cvta_generic_to_shared(p);
}
__device__ __forceinline__ void cp16(uint32_t dst, const void* src) {
    asm volatile("cp.async.cg.shared.global [%0], [%1], 16;\n"
                 :: "r"(dst), "l"(src) : "memory");
}

// ---- prep: tau pack (blocks 0..543) + fold (4 blocks per frame quad) ----
__global__ void __launch_bounds__(256) prep_kernel(
    const int* __restrict__ tau0, const float* __restrict__ x)
{
    __shared__ uint8_t sm[256];
    const int tid = threadIdx.x;

    if (blockIdx.x < PACK_BLOCKS) {
        const int c  = blockIdx.x >> 5;
        const int gb = blockIdx.x & 31;
        const int j  = tid >> 6;
        const int gl = tid & 63;
        const int pr = c * 4 + j;
        uint8_t b = 0;
        if (pr < NFOLD) {
            uint32_t t = (uint32_t)__ldg(&tau0[(int)c_pairA[pr] * GPTS + gb * 64 + gl]);
            b = (uint8_t)((t & 15u) << 4);       // slot*16
        }
        sm[gl * 4 + j] = b;
        __syncthreads();
        if (tid < 64)
            g_tauB[c * GPTS + gb * 64 + tid] = ((const uint32_t*)sm)[tid];
    } else {
        const int q  = blockIdx.x - PACK_BLOCKS;
        const int f4 = q >> 2;                   // frame quad
        const int qt = q & 3;                    // quarter: 272 entries
        float4* dst = g_y4 + f4 * NENT;
        const int base = qt * 272;
        const float* x0 = x + (size_t)(f4 * 4 + 0) * (144 * KLEN);
        const float* x1 = x + (size_t)(f4 * 4 + 1) * (144 * KLEN);
        const float* x2 = x + (size_t)(f4 * 4 + 2) * (144 * KLEN);
        const float* x3 = x + (size_t)(f4 * 4 + 3) * (144 * KLEN);
#pragma unroll 2
        for (int e0 = 0; e0 < 2; e0++) {
            if (e0 == 1 && tid >= 16) break;
            int e = base + e0 * 256 + tid;
            int r = e >> 4, sl = e & 15;
            float4 v = make_float4(0.f, 0.f, 0.f, 0.f);
            if (r < NFOLD) {
                int ra = (int)c_pairA[r] * KLEN + lag_of(sl);
                int rb = (int)c_pairB[r] * KLEN + lag_of((16 - sl) & 15);
                v.x = __ldg(&x0[ra]) + __ldg(&x0[rb]);
                v.y = __ldg(&x1[ra]) + __ldg(&x1[rb]);
                v.z = __ldg(&x2[ra]) + __ldg(&x2[rb]);
                v.w = __ldg(&x3[ra]) + __ldg(&x3[rb]);
            }
            dst[e] = v;
        }
    }
}

// ---------------- gather + fused normalization ----------------
// CTA: f4 = blockIdx.x>>4 (frame quad), s = blockIdx.x&15.  128 threads,
// each owns point g = s*128 + tid for 4 frames.
__global__ void __launch_bounds__(THREADS) srp_gather_kernel(
    const float* __restrict__ x, float* __restrict__ out)
{
    __shared__ __align__(16) float4   xsm[NENT];              // 17408 B
    __shared__ __align__(16) uint32_t stau[NCHUNK * THREADS]; // 8704 B
    __shared__ float red[8][THREADS / 32];
    __shared__ float bcast[8];
    __shared__ int   is_last;

    const int f4  = blockIdx.x >> 4;
    const int s   = blockIdx.x & 15;
    const int tid = threadIdx.x;

    // ---- Async-stage tau slice: stau[c*128+j] = g_tauB[c*2048 + s*128 + j] ----
    {
        const char* src_base = (const char*)g_tauB + (size_t)s * 512;
        uint32_t dst_base = smem_u32(stau);
#pragma unroll
        for (int k = 0; k < 5; k++) {
            int o = tid + k * THREADS;            // 16B-op index, 544 total
            if (o < NCHUNK * 32) {
                int c   = o >> 5;
                int off = (o & 31) * 16;
                cp16(dst_base + c * 512 + off, src_base + (size_t)c * 8192 + off);
            }
        }
    }
    // ---- Async-stage folded y4 table (1088 x 16B) ----
    {
        const char* src = (const char*)(g_y4 + f4 * NENT);
        uint32_t dst = smem_u32(xsm);
#pragma unroll
        for (int k = 0; k < 9; k++) {
            int o = tid + k * THREADS;
            if (o < NENT) cp16(dst + o * 16, src + o * 16);
        }
    }
    asm volatile("cp.async.commit_group;\n" ::: "memory");
    asm volatile("cp.async.wait_group 0;\n" ::: "memory");
    __syncthreads();

    const int g = s * THREADS + tid;
    const char* xbase = (const char*)xsm;

    // 4 packed accumulators: a01_* = frames(0,1), a23_* = frames(2,3)
    unsigned long long a01_0 = 0ull, a01_1 = 0ull;
    unsigned long long a23_0 = 0ull, a23_1 = 0ull;

#pragma unroll
    for (int c = 0; c < NCHUNK; c++) {
        uint32_t w = stau[c * THREADS + tid];     // LDS.32, conflict-free
        const char* cb = xbase + c * 1024;
        // LDS.128 -> ulonglong2: .x = f32x2 frames(0,1), .y = frames(2,3)
        ulonglong2 v0 = *(const ulonglong2*)(cb +   0 + __byte_perm(w, 0, 0x4440));
        ulonglong2 v1 = *(const ulonglong2*)(cb + 256 + __byte_perm(w, 0, 0x4441));
        ulonglong2 v2 = *(const ulonglong2*)(cb + 512 + __byte_perm(w, 0, 0x4442));
        ulonglong2 v3 = *(const ulonglong2*)(cb + 768 + __byte_perm(w, 0, 0x4443));
        asm("add.rn.f32x2 %0, %0, %1;" : "+l"(a01_0) : "l"(v0.x));
        asm("add.rn.f32x2 %0, %0, %1;" : "+l"(a23_0) : "l"(v0.y));
        asm("add.rn.f32x2 %0, %0, %1;" : "+l"(a01_1) : "l"(v1.x));
        asm("add.rn.f32x2 %0, %0, %1;" : "+l"(a23_1) : "l"(v1.y));
        asm("add.rn.f32x2 %0, %0, %1;" : "+l"(a01_0) : "l"(v2.x));
        asm("add.rn.f32x2 %0, %0, %1;" : "+l"(a23_0) : "l"(v2.y));
        asm("add.rn.f32x2 %0, %0, %1;" : "+l"(a01_1) : "l"(v3.x));
        asm("add.rn.f32x2 %0, %0, %1;" : "+l"(a23_1) : "l"(v3.y));
    }

    // combine ping-pong halves, unpack to per-frame values
    asm("add.rn.f32x2 %0, %0, %1;" : "+l"(a01_0) : "l"(a01_1));
    asm("add.rn.f32x2 %0, %0, %1;" : "+l"(a23_0) : "l"(a23_1));
    float2 p01 = *(float2*)&a01_0;
    float2 p23 = *(float2*)&a23_0;
    float v[4] = { p01.x, p01.y, p23.x, p23.y };

#pragma unroll
    for (int fr = 0; fr < 4; fr++)
        out[(size_t)(f4 * 4 + fr) * GPTS + g] = v[fr];

    // ---- CTA-local partial sum/max per frame ----
    float ps[4], pm[4];
#pragma unroll
    for (int fr = 0; fr < 4; fr++) { ps[fr] = v[fr]; pm[fr] = v[fr]; }
#pragma unroll
    for (int o = 16; o > 0; o >>= 1) {
#pragma unroll
        for (int fr = 0; fr < 4; fr++) {
            ps[fr] += __shfl_xor_sync(0xFFFFFFFFu, ps[fr], o);
            pm[fr] = fmaxf(pm[fr], __shfl_xor_sync(0xFFFFFFFFu, pm[fr], o));
        }
    }
    int wid = tid >> 5, lane = tid & 31;
    if (lane == 0) {
#pragma unroll
        for (int fr = 0; fr < 4; fr++) {
            red[fr * 2][wid]     = ps[fr];
            red[fr * 2 + 1][wid] = pm[fr];
        }
    }
    __syncthreads();

    if (tid == 0) {
#pragma unroll
        for (int fr = 0; fr < 4; fr++) {
            float cs = 0.f, cm = -3.0e38f;
#pragma unroll
            for (int wq = 0; wq < THREADS / 32; wq++) {
                cs += red[fr * 2][wq];
                cm = fmaxf(cm, red[fr * 2 + 1][wq]);
            }
            ws_s[(f4 * 4 + fr) * NSPLIT + s] = cs;
            ws_m[(f4 * 4 + fr) * NSPLIT + s] = cm;
        }
        __threadfence();
        int old = atomicAdd(&ws_c[f4], 1);
        is_last = (old == NSPLIT - 1) ? 1 : 0;
    }
    __syncthreads();
    if (!is_last) return;

    // ---- Last CTA of this frame quad: normalize 4 frames ----
    if (tid == 0) {
        __threadfence();
        ws_c[f4] = 0;                            // reset for next graph replay
        const float EPS = 1e-12f;
#pragma unroll
        for (int fr = 0; fr < 4; fr++) {
            int f = f4 * 4 + fr;
            float tot = 0.f, mm = -3.0e38f;
#pragma unroll
            for (int k = 0; k < NSPLIT; k++) {   // fixed order: deterministic
                tot += ws_s[f * NSPLIT + k];
                mm = fmaxf(mm, ws_m[f * NSPLIT + k]);
            }
            float mean = tot * (1.0f / (float)GPTS);
            bcast[fr * 2]     = mean;
            bcast[fr * 2 + 1] = 1.0f / (mm - mean + EPS);
        }
    }
    __syncthreads();

    const float EPS = 1e-12f;
#pragma unroll
    for (int fr = 0; fr < 4; fr++) {
        float* of  = out + (size_t)(f4 * 4 + fr) * GPTS;
        float mean = bcast[fr * 2];
        float inv  = bcast[fr * 2 + 1];
#pragma unroll
        for (int e = 0; e < 4; e++) {
            float4 q = *(const float4*)(of + e * 512 + tid * 4);
            q.x = (q.x - mean + EPS) * inv;
            q.y = (q.y - mean + EPS) * inv;
            q.z = (q.z - mean + EPS) * inv;
            q.w = (q.w - mean + EPS) * inv;
            *(float4*)(of + e * 512 + tid * 4) = q;
        }
    }
}

extern "C" void kernel_launch(void* const* d_in, const int* in_sizes, int n_in,
                              void* d_out, int out_size)
{
    const float* x;
    const int*   tau0;
    if (in_sizes[0] == 144 * GPTS) {
        tau0 = (const int*)d_in[0];
        x    = (const float*)d_in[1];
    } else {
        x    = (const float*)d_in[0];
        tau0 = (const int*)d_in[1];
    }

    int nframes = out_size / GPTS;      // 256
    int nf4     = nframes / 4;          // 64 frame quads

    prep_kernel<<<PACK_BLOCKS + nf4 * FOLD_SPLIT, 256>>>(tau0, x);
    srp_gather_kernel<<<nf4 * NSPLIT, THREADS>>>(x, (float*)d_out);
}

// round 17
// speedup vs baseline: 1.0118x; 1.0118x over previous
#include <cuda_runtime.h>
#include <stdint.h>

// SRP map on GB300 — round 13.
//
// maps[f,g] = sum_{k!=l} x[f, k*12+l, tau0[k,l,g]], then per-frame
// zero-mean + /max.
//
// R13(+): exactly the best-measured R13 configuration (2 frames/CTA,
// LDS.64 + f32x2, NSPLIT=16, 128 threads, cp.async staging, fused norm)
// with SLOT COMPRESSION 16 -> 11 (exact: |lag| <= 5 strictly, wrapped
// {0..5} U {507..511}; slot = t<256 ? t : t-501 is bijective onto 0..10).
// Folded row 88B, xsm 5984B; total smem ~15KB -> reg-limited 11 CTAs/SM
// (44 warps, 69% occ ceiling vs 50% when smem-limited at 26KB).
// 4-frame variants (R15/R16) are dead: reg-fat + LDS.128 bank hazard.

#define KLEN    512
#define GPTS    2048
#define THREADS 128
#define NFOLD   66
#define NROWS   68                  // padded to 17 chunks of 4
#define NSLOT   11
#define NENT    (NROWS * NSLOT)     // 748 float2 entries = 5984 B
#define NCHUNK  17
#define NSPLIT  16
#define MAXF2   256
#define PACK_BLOCKS (NCHUNK * 32)   // 544
#define FOLD_SPLIT 4

__constant__ uint8_t c_pairA[NFOLD] = {
  1,2,3,4,5,6,7,8,9,10,11,
  14,15,16,17,18,19,20,21,22,23,
  27,28,29,30,31,32,33,34,35,
  40,41,42,43,44,45,46,47,
  53,54,55,56,57,58,59,
  66,67,68,69,70,71,
  79,80,81,82,83,
  92,93,94,95,
  105,106,107,
  118,119,
  131};
__constant__ uint8_t c_pairB[NFOLD] = {
  12,24,36,48,60,72,84,96,108,120,132,
  25,37,49,61,73,85,97,109,121,133,
  38,50,62,74,86,98,110,122,134,
  51,63,75,87,99,111,123,135,
  64,76,88,100,112,124,136,
  77,89,101,113,125,137,
  90,102,114,126,138,
  103,115,127,139,
  116,128,140,
  129,141,
  142};

// g_tauB[c*2048+g]: 4 bytes = slot*8 (LDS.64 byte offset) for pairs 4c..4c+3.
__device__ __align__(16) uint32_t g_tauB[NCHUNK * GPTS];
// folded x table: y[f2][entry], entry = r*11 + slot, value = (frame f0, f1)
__device__ __align__(16) float2 g_y[MAXF2 * NENT];
// last-arrival workspace
__device__ float ws_s[MAXF2 * 2 * NSPLIT];
__device__ float ws_m[MAXF2 * 2 * NSPLIT];
__device__ int   ws_c[MAXF2];            // zero-init; self-resetting

// slot (0..10) -> circular lag
__device__ __forceinline__ int lag_of_slot(int s) { return (s < 6) ? s : (s + 501); }
// folded partner: lag(-s): slot 0 -> 0, else 11-s
__device__ __forceinline__ int neg_slot(int s) { return (s == 0) ? 0 : (11 - s); }

__device__ __forceinline__ uint32_t smem_u32(const void* p) {
    return (uint32_t)__cvta_generic_to_shared(p);
}
__device__ __forceinline__ void cp16(uint32_t dst, const void* src) {
    asm volatile("cp.async.cg.shared.global [%0], [%1], 16;\n"
                 :: "r"(dst), "l"(src) : "memory");
}

// ---- prep: tau pack (blocks 0..543) + fold (4 blocks per frame pair) ----
__global__ void __launch_bounds__(256) prep_kernel(
    const int* __restrict__ tau0, const float* __restrict__ x)
{
    __shared__ uint8_t sm[256];
    const int tid = threadIdx.x;

    if (blockIdx.x < PACK_BLOCKS) {
        const int c  = blockIdx.x >> 5;
        const int gb = blockIdx.x & 31;
        const int j  = tid >> 6;
        const int gl = tid & 63;
        const int pr = c * 4 + j;
        uint8_t b = 0;
        if (pr < NFOLD) {
            uint32_t t = (uint32_t)__ldg(&tau0[(int)c_pairA[pr] * GPTS + gb * 64 + gl]);
            uint32_t slot = (t < 256u) ? t : (t - 501u);   // 0..10
            b = (uint8_t)(slot << 3);                      // slot*8
        }
        sm[gl * 4 + j] = b;
        __syncthreads();
        if (tid < 64)
            g_tauB[c * GPTS + gb * 64 + tid] = ((const uint32_t*)sm)[tid];
    } else {
        const int q  = blockIdx.x - PACK_BLOCKS;
        const int f2 = q >> 2;                   // frame pair
        const int qt = q & 3;                    // quarter: 187 entries
        const float* xa = x + (size_t)(f2 * 2)     * (144 * KLEN);
        const float* xb = x + (size_t)(f2 * 2 + 1) * (144 * KLEN);
        float2* dst = g_y + f2 * NENT;
        int e = qt * 187 + tid;
        if (tid < 187 && e < NENT) {
            int r  = e / NSLOT;
            int sl = e - r * NSLOT;
            float2 v = make_float2(0.0f, 0.0f);
            if (r < NFOLD) {
                int ra = (int)c_pairA[r] * KLEN + lag_of_slot(sl);
                int rb = (int)c_pairB[r] * KLEN + lag_of_slot(neg_slot(sl));
                v.x = __ldg(&xa[ra]) + __ldg(&xa[rb]);
                v.y = __ldg(&xb[ra]) + __ldg(&xb[rb]);
            }
            dst[e] = v;
        }
    }
}

// ---------------- gather + fused normalization ----------------
// CTA: f2 = blockIdx.x>>4 (frame pair), s = blockIdx.x&15.  128 threads,
// each owns point g = s*128 + tid.
__global__ void __launch_bounds__(THREADS) srp_gather_kernel(
    const float* __restrict__ x, float* __restrict__ out)
{
    __shared__ __align__(16) float2   xsm[NENT + 4];          // 6016 B
    __shared__ __align__(16) uint32_t stau[NCHUNK * THREADS]; // 8704 B
    __shared__ float red[4][THREADS / 32];
    __shared__ float bcast[4];
    __shared__ int   is_last;

    const int f2  = blockIdx.x >> 4;
    const int s   = blockIdx.x & 15;
    const int tid = threadIdx.x;
    const int f0  = f2 * 2;
    const int f1  = f0 + 1;

    // ---- Async-stage tau slice: stau[c*128+j] = g_tauB[c*2048 + s*128 + j] ----
    {
        const char* src_base = (const char*)g_tauB + (size_t)s * 512;
        uint32_t dst_base = smem_u32(stau);
#pragma unroll
        for (int k = 0; k < 5; k++) {
            int o = tid + k * THREADS;            // 16B-op index, 544 total
            if (o < NCHUNK * 32) {
                int c   = o >> 5;
                int off = (o & 31) * 16;
                cp16(dst_base + c * 512 + off, src_base + (size_t)c * 8192 + off);
            }
        }
    }
    // ---- Async-stage folded y table (374 x 16B) ----
    {
        const char* src = (const char*)(g_y + f2 * NENT);
        uint32_t dst = smem_u32(xsm);
#pragma unroll
        for (int k = 0; k < 3; k++) {
            int o = tid + k * THREADS;
            if (o < (NENT * 8 + 15) / 16) cp16(dst + o * 16, src + o * 16);
        }
    }
    asm volatile("cp.async.commit_group;\n" ::: "memory");
    asm volatile("cp.async.wait_group 0;\n" ::: "memory");
    __syncthreads();

    const int g = s * THREADS + tid;
    const char* xbase = (const char*)xsm;

    unsigned long long a0 = 0ull, a1 = 0ull, a2 = 0ull, a3 = 0ull;
#pragma unroll
    for (int c = 0; c < NCHUNK; c++) {
        uint32_t w = stau[c * THREADS + tid];     // LDS.32, conflict-free
        const char* cb = xbase + c * 352;         // 4 pairs x 88B rows
        unsigned long long v0 = *(const unsigned long long*)(cb +   0 + __byte_perm(w, 0, 0x4440));
        unsigned long long v1 = *(const unsigned long long*)(cb +  88 + __byte_perm(w, 0, 0x4441));
        unsigned long long v2 = *(const unsigned long long*)(cb + 176 + __byte_perm(w, 0, 0x4442));
        unsigned long long v3 = *(const unsigned long long*)(cb + 264 + __byte_perm(w, 0, 0x4443));
        asm("add.rn.f32x2 %0, %0, %1;" : "+l"(a0) : "l"(v0));
        asm("add.rn.f32x2 %0, %0, %1;" : "+l"(a1) : "l"(v1));
        asm("add.rn.f32x2 %0, %0, %1;" : "+l"(a2) : "l"(v2));
        asm("add.rn.f32x2 %0, %0, %1;" : "+l"(a3) : "l"(v3));
    }

    float2 t0 = *(float2*)&a0, t1 = *(float2*)&a1;
    float2 t2 = *(float2*)&a2, t3 = *(float2*)&a3;
    float v0 = (t0.x + t1.x) + (t2.x + t3.x);     // frame f0, point g
    float v1 = (t0.y + t1.y) + (t2.y + t3.y);     // frame f1, point g

    float* o0 = out + (size_t)f0 * GPTS;
    float* o1 = out + (size_t)f1 * GPTS;
    o0[g] = v0;
    o1[g] = v1;

    // ---- CTA-local partial sum/max for both frames ----
    float s0 = v0, m0 = v0, s1 = v1, m1 = v1;
#pragma unroll
    for (int o = 16; o > 0; o >>= 1) {
        s0 += __shfl_xor_sync(0xFFFFFFFFu, s0, o);
        m0 = fmaxf(m0, __shfl_xor_sync(0xFFFFFFFFu, m0, o));
        s1 += __shfl_xor_sync(0xFFFFFFFFu, s1, o);
        m1 = fmaxf(m1, __shfl_xor_sync(0xFFFFFFFFu, m1, o));
    }
    int wid = tid >> 5, lane = tid & 31;
    if (lane == 0) {
        red[0][wid] = s0; red[1][wid] = m0;
        red[2][wid] = s1; red[3][wid] = m1;
    }
    __syncthreads();

    if (tid == 0) {
        float cs0 = 0.f, cm0 = -3.0e38f, cs1 = 0.f, cm1 = -3.0e38f;
#pragma unroll
        for (int wq = 0; wq < THREADS / 32; wq++) {
            cs0 += red[0][wq]; cm0 = fmaxf(cm0, red[1][wq]);
            cs1 += red[2][wq]; cm1 = fmaxf(cm1, red[3][wq]);
        }
        ws_s[(f0 * NSPLIT) + s] = cs0;  ws_m[(f0 * NSPLIT) + s] = cm0;
        ws_s[(f1 * NSPLIT) + s] = cs1;  ws_m[(f1 * NSPLIT) + s] = cm1;
        __threadfence();
        int old = atomicAdd(&ws_c[f2], 1);
        is_last = (old == NSPLIT - 1) ? 1 : 0;
    }
    __syncthreads();
    if (!is_last) return;

    // ---- Last CTA of this frame pair: normalize both frames ----
    if (tid == 0) {
        __threadfence();
        ws_c[f2] = 0;                            // reset for next graph replay
        const float EPS = 1e-12f;
#pragma unroll
        for (int fr = 0; fr < 2; fr++) {
            int f = f0 + fr;
            float tot = 0.f, mm = -3.0e38f;
#pragma unroll
            for (int k = 0; k < NSPLIT; k++) {   // fixed order: deterministic
                tot += ws_s[f * NSPLIT + k];
                mm = fmaxf(mm, ws_m[f * NSPLIT + k]);
            }
            float mean = tot * (1.0f / (float)GPTS);
            bcast[fr * 2]     = mean;
            bcast[fr * 2 + 1] = 1.0f / (mm - mean + EPS);
        }
    }
    __syncthreads();

    const float EPS = 1e-12f;
#pragma unroll
    for (int fr = 0; fr < 2; fr++) {
        float* of  = (fr == 0) ? o0 : o1;
        float mean = bcast[fr * 2];
        float inv  = bcast[fr * 2 + 1];
#pragma unroll
        for (int e = 0; e < 4; e++) {
            float4 q = *(const float4*)(of + e * 512 + tid * 4);
            q.x = (q.x - mean + EPS) * inv;
            q.y = (q.y - mean + EPS) * inv;
            q.z = (q.z - mean + EPS) * inv;
            q.w = (q.w - mean + EPS) * inv;
            *(float4*)(of + e * 512 + tid * 4) = q;
        }
    }
}

extern "C" void kernel_launch(void* const* d_in, const int* in_sizes, int n_in,
                              void* d_out, int out_size)
{
    const float* x;
    const int*   tau0;
    if (in_sizes[0] == 144 * GPTS) {
        tau0 = (const int*)d_in[0];
        x    = (const float*)d_in[1];
    } else {
        x    = (const float*)d_in[0];
        tau0 = (const int*)d_in[1];
    }

    int nframes = out_size / GPTS;      // 256
    int nf2     = nframes / 2;          // 128 frame pairs

    prep_kernel<<<PACK_BLOCKS + nf2 * FOLD_SPLIT, 256>>>(tau0, x);
    srp_gather_kernel<<<nf2 * NSPLIT, THREADS>>>(x, (float*)d_out);
}